// round 13
// baseline (speedup 1.0000x reference)
#include <cuda_runtime.h>
#include <cuda_fp16.h>
#include <stdint.h>
#include <math.h>

#define B_ 8192
#define D_ 2048
#define C_ 4096
#define K_ 1000
#define KPAD_ 1024

// smem geometry: K-chunk 128 halfs = 256B data + 16B pad per row
#define ROWB 272
#define A_ROWS 256
#define B_ROWS 128
#define PART_A (A_ROWS * ROWB)      // 69632
#define PART_B (B_ROWS * ROWB)      // 34816
#define S_STAGE (PART_A + PART_B)   // 104448
#define NSTAGE 2
#define S_SMEM (NSTAGE * S_STAGE)   // 208896  (1 CTA/SM)

// ---------------------------------------------------------------------------
// Device scratch
// ---------------------------------------------------------------------------
__device__ __align__(128) __half g_xh[(size_t)B_ * D_];
__device__ __align__(128) __half g_ch[(size_t)C_ * D_];
__device__ __align__(128) __half g_wh[(size_t)KPAD_ * C_];
__device__ __align__(128) __half g_ah[(size_t)B_ * C_];
__device__ float g_x2[B_], g_c2[C_], g_rowsum[B_];

// ---------------------------------------------------------------------------
// PTX helpers
// ---------------------------------------------------------------------------
__device__ __forceinline__ uint32_t smem_u32(const void* p) {
    uint32_t a;
    asm("{ .reg .u64 t; cvta.to.shared.u64 t, %1; cvt.u32.u64 %0, t; }"
        : "=r"(a) : "l"(p));
    return a;
}

__device__ __forceinline__ void ldsm_x4(uint32_t& r0, uint32_t& r1, uint32_t& r2,
                                        uint32_t& r3, uint32_t addr) {
    asm volatile("ldmatrix.sync.aligned.m8n8.x4.shared.b16 {%0,%1,%2,%3}, [%4];"
                 : "=r"(r0), "=r"(r1), "=r"(r2), "=r"(r3) : "r"(addr));
}

__device__ __forceinline__ void mma_f16(float c[4], const uint32_t a[4],
                                        const uint32_t b[2]) {
    asm volatile(
        "mma.sync.aligned.m16n8k16.row.col.f32.f16.f16.f32 "
        "{%0,%1,%2,%3}, {%4,%5,%6,%7}, {%8,%9}, {%0,%1,%2,%3};"
        : "+f"(c[0]), "+f"(c[1]), "+f"(c[2]), "+f"(c[3])
        : "r"(a[0]), "r"(a[1]), "r"(a[2]), "r"(a[3]), "r"(b[0]), "r"(b[1]));
}

__device__ __forceinline__ void cp16(uint32_t dst, const void* src) {
    asm volatile("cp.async.cg.shared.global [%0], [%1], 16;"
                 :: "r"(dst), "l"(src) : "memory");
}
#define CP_COMMIT() asm volatile("cp.async.commit_group;" ::: "memory")
template <int N>
__device__ __forceinline__ void cp_wait() {
    asm volatile("cp.async.wait_group %0;" :: "n"(N) : "memory");
}

// ---------------------------------------------------------------------------
// Prologue kernels
// ---------------------------------------------------------------------------
__global__ void splitx_kernel(const float* __restrict__ x, __half* __restrict__ xh) {
    const int row = blockIdx.x;
    const float4* p = reinterpret_cast<const float4*>(x + (size_t)row * D_);
    float s = 0.f;
    for (int i = threadIdx.x; i < D_ / 4; i += blockDim.x) {
        float4 v = p[i];
        s += v.x * v.x + v.y * v.y + v.z * v.z + v.w * v.w;
        __half h[4] = {__float2half(v.x), __float2half(v.y),
                       __float2half(v.z), __float2half(v.w)};
        *reinterpret_cast<uint2*>(xh + (size_t)row * D_ + i * 4) =
            *reinterpret_cast<uint2*>(h);
    }
    #pragma unroll
    for (int o = 16; o; o >>= 1) s += __shfl_xor_sync(0xffffffffu, s, o);
    __shared__ float ws[8];
    if ((threadIdx.x & 31) == 0) ws[threadIdx.x >> 5] = s;
    __syncthreads();
    if (threadIdx.x == 0) {
        float t = 0.f;
        #pragma unroll
        for (int i = 0; i < 8; i++) t += ws[i];
        g_x2[row] = t;
        g_rowsum[row] = 0.f;
    }
}

__global__ void splitc_kernel(const float* __restrict__ cen, __half* __restrict__ ch) {
    const int row = blockIdx.x;
    const float4* p = reinterpret_cast<const float4*>(cen + (size_t)row * D_);
    float s = 0.f;
    for (int i = threadIdx.x; i < D_ / 4; i += blockDim.x) {
        float4 v = p[i];
        s += v.x * v.x + v.y * v.y + v.z * v.z + v.w * v.w;
        __half h[4] = {__float2half(v.x), __float2half(v.y),
                       __float2half(v.z), __float2half(v.w)};
        *reinterpret_cast<uint2*>(ch + (size_t)row * D_ + i * 4) =
            *reinterpret_cast<uint2*>(h);
    }
    #pragma unroll
    for (int o = 16; o; o >>= 1) s += __shfl_xor_sync(0xffffffffu, s, o);
    __shared__ float ws[8];
    if ((threadIdx.x & 31) == 0) ws[threadIdx.x >> 5] = s;
    __syncthreads();
    if (threadIdx.x == 0) {
        float t = 0.f;
        #pragma unroll
        for (int i = 0; i < 8; i++) t += ws[i];
        g_c2[row] = t;
    }
}

__global__ void splitW_kernel(const float* __restrict__ W) {
    int i = blockIdx.x * blockDim.x + threadIdx.x;
    if (i >= KPAD_ * C_ / 4) return;
    int r = i >> 10;
    int c0 = (i & 1023) * 4;
    float f[4] = {0.f, 0.f, 0.f, 0.f};
    if (r < K_) {
        float4 v = *reinterpret_cast<const float4*>(W + (size_t)r * C_ + c0);
        f[0] = v.x; f[1] = v.y; f[2] = v.z; f[3] = v.w;
    }
    __half h[4] = {__float2half(f[0]), __float2half(f[1]),
                   __float2half(f[2]), __float2half(f[3])};
    *reinterpret_cast<uint2*>(g_wh + (size_t)r * C_ + c0) = *reinterpret_cast<uint2*>(h);
}

// ---------------------------------------------------------------------------
// fp16 1-pass GEMM: CTA tile 256x128, 8 warps (4x2, warp tile 64x64),
// K-chunk 128, 2-stage cp.async pipeline (load c+1 overlaps compute c),
// one __syncthreads per chunk, 1 CTA/SM.
// MODE 0 (GEMM1): A=xh, B=ch. Epilogue: shifted RBF -> fp16 a' + rowsum.
//                 (softmax shift uses c2mean ~= 2048; exact value irrelevant
//                  to correctness, only to fp16 dynamic-range placement)
// MODE 1 (GEMM2): A=a', B=wh. Epilogue: out = acc/rowsum + bias.
// ---------------------------------------------------------------------------
template <int KDIM, int MODE>
__global__ __launch_bounds__(256, 1) void gemm_f16_kernel(
    const __half* __restrict__ Ah, const __half* __restrict__ Bh,
    const float* __restrict__ beta, const float* __restrict__ bias,
    float* __restrict__ out)
{
    constexpr int NCH = KDIM / 128;
    extern __shared__ char smem[];
    const uint32_t sb = smem_u32(smem);
    const int tid = threadIdx.x;
    const int w = tid >> 5, lane = tid & 31;
    const int warp_m = w >> 1, warp_n = w & 1;   // 4x2 grid of 64x64 tiles
    const int bx = blockIdx.x, by = blockIdx.y;

    // ---- loader mapping ----
    // A: thread t loads its row (256 rows), 16 granules of 16B (256B data).
    // B: thread t loads row t&127, granules (t>>7)*8 .. +7.
    const __half* srcA = Ah + (size_t)(by * 256 + tid) * KDIM;
    const int brow = tid & 127;
    const int bgb = (tid >> 7) * 8;
    const __half* srcB = Bh + (size_t)(bx * 128 + brow) * KDIM + bgb * 8;
    const uint32_t dA = tid * ROWB;
    const uint32_t dB = PART_A + brow * ROWB + bgb * 16;

    float acc[4][8][4];
    #pragma unroll
    for (int mt = 0; mt < 4; mt++)
        #pragma unroll
        for (int nt = 0; nt < 8; nt++)
            #pragma unroll
            for (int q = 0; q < 4; q++) acc[mt][nt][q] = 0.f;

#define S_ISSUE(stage, c) do {                                               \
        const uint32_t stb_ = sb + (stage) * S_STAGE;                        \
        const int co_ = (c) * 128;                                           \
        _Pragma("unroll")                                                    \
        for (int g_ = 0; g_ < 16; g_++)                                      \
            cp16(stb_ + dA + g_ * 16, srcA + co_ + g_ * 8);                  \
        _Pragma("unroll")                                                    \
        for (int g_ = 0; g_ < 8; g_++)                                       \
            cp16(stb_ + dB + g_ * 16, srcB + co_ + g_ * 8);                  \
        CP_COMMIT();                                                         \
    } while (0)

    S_ISSUE(0, 0);

    const uint32_t aoff = (uint32_t)(warp_m * 64 + (lane & 15)) * ROWB +
                          (uint32_t)((lane >> 4) << 3) * 2;
    const uint32_t boff = PART_A +
                          (uint32_t)(warp_n * 64 + (lane & 7) + ((lane >> 4) << 3)) * ROWB +
                          (uint32_t)(lane & 8) * 2;

    #pragma unroll 1
    for (int c = 0; c < NCH; c++) {
        cp_wait<0>();            // chunk c fully resident
        __syncthreads();         // all warps done with chunk c-1's stage
        if (c + 1 < NCH) S_ISSUE((c + 1) & 1, c + 1);   // overlaps compute below

        const uint32_t bufb = sb + (c & 1) * S_STAGE;
        #pragma unroll
        for (int ks = 0; ks < 8; ks++) {
            const uint32_t kso = ks * 32;
            uint32_t AH[4][4], BB[8][2];
            #pragma unroll
            for (int mt = 0; mt < 4; mt++)
                ldsm_x4(AH[mt][0], AH[mt][1], AH[mt][2], AH[mt][3],
                        bufb + aoff + kso + mt * 16 * ROWB);
            #pragma unroll
            for (int np = 0; np < 4; np++) {
                uint32_t r0, r1, r2, r3;
                ldsm_x4(r0, r1, r2, r3,
                        bufb + boff + kso + np * 16 * ROWB);
                BB[np * 2][0] = r0; BB[np * 2][1] = r1;
                BB[np * 2 + 1][0] = r2; BB[np * 2 + 1][1] = r3;
            }
            #pragma unroll
            for (int mt = 0; mt < 4; mt++)
                #pragma unroll
                for (int nt = 0; nt < 8; nt++)
                    mma_f16(acc[mt][nt], AH[mt], BB[nt]);
        }
    }
#undef S_ISSUE

    // ------------------------------ epilogue -------------------------------
    const int lr = lane >> 2;
    const int lc = (lane & 3) * 2;

    if (MODE == 0) {
        const float c2m = 2048.0f;   // E[c2] for N(0,1)^2048; exact value non-critical
        #pragma unroll
        for (int mt = 0; mt < 4; mt++) {
            #pragma unroll
            for (int h = 0; h < 2; h++) {
                const int row = by * 256 + warp_m * 64 + mt * 16 + h * 8 + lr;
                const float x2v = g_x2[row];
                const float shift = sqrtf(x2v + c2m) - 4.0f;
                float rsum = 0.f;
                #pragma unroll
                for (int nt = 0; nt < 8; nt++) {
                    const int col = bx * 128 + warp_n * 64 + nt * 8 + lc;
                    const float dd0 = acc[mt][nt][h * 2 + 0];
                    const float dd1 = acc[mt][nt][h * 2 + 1];
                    float sq0 = x2v + g_c2[col]     - 2.f * dd0;
                    float sq1 = x2v + g_c2[col + 1] - 2.f * dd1;
                    float e0 = fminf(shift - beta[col]     * sqrtf(fmaxf(sq0, 0.f)), 10.f);
                    float e1 = fminf(shift - beta[col + 1] * sqrtf(fmaxf(sq1, 0.f)), 10.f);
                    float v0 = __expf(e0);
                    float v1 = __expf(e1);
                    rsum += v0 + v1;
                    __half h0 = __float2half(v0);
                    __half h1 = __float2half(v1);
                    uint32_t hp = (uint32_t)__half_as_ushort(h0) |
                                  ((uint32_t)__half_as_ushort(h1) << 16);
                    *reinterpret_cast<uint32_t*>(&g_ah[(size_t)row * C_ + col]) = hp;
                }
                rsum += __shfl_xor_sync(0xffffffffu, rsum, 1);
                rsum += __shfl_xor_sync(0xffffffffu, rsum, 2);
                if ((lane & 3) == 0) atomicAdd(&g_rowsum[row], rsum);
            }
        }
    } else {
        #pragma unroll
        for (int mt = 0; mt < 4; mt++) {
            #pragma unroll
            for (int h = 0; h < 2; h++) {
                const int row = by * 256 + warp_m * 64 + mt * 16 + h * 8 + lr;
                const float inv = 1.0f / g_rowsum[row];
                #pragma unroll
                for (int nt = 0; nt < 8; nt++) {
                    const int col = bx * 128 + warp_n * 64 + nt * 8 + lc;
                    if (col < K_) {
                        float2 bb = *reinterpret_cast<const float2*>(&bias[col]);
                        float2 o;
                        o.x = acc[mt][nt][h * 2 + 0] * inv + bb.x;
                        o.y = acc[mt][nt][h * 2 + 1] * inv + bb.y;
                        *reinterpret_cast<float2*>(&out[(size_t)row * K_ + col]) = o;
                    }
                }
            }
        }
    }
}

// ---------------------------------------------------------------------------
extern "C" void kernel_launch(void* const* d_in, const int* in_sizes, int n_in,
                              void* d_out, int out_size) {
    const float* x       = (const float*)d_in[0];
    const float* centers = (const float*)d_in[1];
    const float* beta    = (const float*)d_in[2];
    const float* W       = (const float*)d_in[3];
    const float* bias    = (const float*)d_in[4];
    float* out = (float*)d_out;

    __half *xh, *ch, *wh, *ah;
    cudaGetSymbolAddress((void**)&xh, g_xh);
    cudaGetSymbolAddress((void**)&ch, g_ch);
    cudaGetSymbolAddress((void**)&wh, g_wh);
    cudaGetSymbolAddress((void**)&ah, g_ah);

    cudaFuncSetAttribute(gemm_f16_kernel<D_, 0>,
                         cudaFuncAttributeMaxDynamicSharedMemorySize, S_SMEM);
    cudaFuncSetAttribute(gemm_f16_kernel<C_, 1>,
                         cudaFuncAttributeMaxDynamicSharedMemorySize, S_SMEM);

    splitx_kernel<<<B_, 256>>>(x, xh);
    splitc_kernel<<<C_, 256>>>(centers, ch);
    {
        int n4 = KPAD_ * C_ / 4;
        splitW_kernel<<<(n4 + 255) / 256, 256>>>(W);
    }

    dim3 g1(C_ / 128, B_ / 256);            // (32, 32)
    gemm_f16_kernel<D_, 0><<<g1, 256, S_SMEM>>>(xh, ch, beta, bias, out);

    dim3 g2(KPAD_ / 128, B_ / 256);         // (8, 32)
    gemm_f16_kernel<C_, 1><<<g2, 256, S_SMEM>>>(ah, wh, beta, bias, out);
}

// round 16
// speedup vs baseline: 1.5351x; 1.5351x over previous
#include <cuda_runtime.h>
#include <cuda_fp16.h>
#include <stdint.h>
#include <math.h>

#define B_ 8192
#define D_ 2048
#define C_ 4096
#define K_ 1000
#define KPAD_ 1024

// smem geometry: K-chunk 64 halfs = 128B data + 16B pad per row
#define ROWB 144
#define A_ROWS 256
#define B_ROWS 128
#define PART_A (A_ROWS * ROWB)      // 36864
#define PART_B (B_ROWS * ROWB)      // 18432
#define S_STAGE (PART_A + PART_B)   // 55296
#define NSTAGE 4
#define S_SMEM (NSTAGE * S_STAGE)   // 221184 (1 CTA/SM)

// ---------------------------------------------------------------------------
// Device scratch
// ---------------------------------------------------------------------------
__device__ __align__(128) __half g_xh[(size_t)B_ * D_];
__device__ __align__(128) __half g_ch[(size_t)C_ * D_];
__device__ __align__(128) __half g_wh[(size_t)KPAD_ * C_];
__device__ __align__(128) __half g_ah[(size_t)B_ * C_];
__device__ float g_x2[B_], g_c2[C_], g_rowsum[B_];

// ---------------------------------------------------------------------------
// PTX helpers
// ---------------------------------------------------------------------------
__device__ __forceinline__ uint32_t smem_u32(const void* p) {
    uint32_t a;
    asm("{ .reg .u64 t; cvta.to.shared.u64 t, %1; cvt.u32.u64 %0, t; }"
        : "=r"(a) : "l"(p));
    return a;
}

__device__ __forceinline__ void ldsm_x4(uint32_t& r0, uint32_t& r1, uint32_t& r2,
                                        uint32_t& r3, uint32_t addr) {
    asm volatile("ldmatrix.sync.aligned.m8n8.x4.shared.b16 {%0,%1,%2,%3}, [%4];"
                 : "=r"(r0), "=r"(r1), "=r"(r2), "=r"(r3) : "r"(addr));
}

__device__ __forceinline__ void mma_f16(float c[4], const uint32_t a[4],
                                        const uint32_t b[2]) {
    asm volatile(
        "mma.sync.aligned.m16n8k16.row.col.f32.f16.f16.f32 "
        "{%0,%1,%2,%3}, {%4,%5,%6,%7}, {%8,%9}, {%0,%1,%2,%3};"
        : "+f"(c[0]), "+f"(c[1]), "+f"(c[2]), "+f"(c[3])
        : "r"(a[0]), "r"(a[1]), "r"(a[2]), "r"(a[3]), "r"(b[0]), "r"(b[1]));
}

__device__ __forceinline__ void cp16(uint32_t dst, const void* src) {
    asm volatile("cp.async.cg.shared.global [%0], [%1], 16;"
                 :: "r"(dst), "l"(src) : "memory");
}
#define CP_COMMIT() asm volatile("cp.async.commit_group;" ::: "memory")
template <int N>
__device__ __forceinline__ void cp_wait() {
    asm volatile("cp.async.wait_group %0;" :: "n"(N) : "memory");
}

// ---------------------------------------------------------------------------
// Prologue kernels
// ---------------------------------------------------------------------------
__global__ void splitx_kernel(const float* __restrict__ x, __half* __restrict__ xh) {
    const int row = blockIdx.x;
    const float4* p = reinterpret_cast<const float4*>(x + (size_t)row * D_);
    float s = 0.f;
    for (int i = threadIdx.x; i < D_ / 4; i += blockDim.x) {
        float4 v = p[i];
        s += v.x * v.x + v.y * v.y + v.z * v.z + v.w * v.w;
        __half h[4] = {__float2half(v.x), __float2half(v.y),
                       __float2half(v.z), __float2half(v.w)};
        *reinterpret_cast<uint2*>(xh + (size_t)row * D_ + i * 4) =
            *reinterpret_cast<uint2*>(h);
    }
    #pragma unroll
    for (int o = 16; o; o >>= 1) s += __shfl_xor_sync(0xffffffffu, s, o);
    __shared__ float ws[8];
    if ((threadIdx.x & 31) == 0) ws[threadIdx.x >> 5] = s;
    __syncthreads();
    if (threadIdx.x == 0) {
        float t = 0.f;
        #pragma unroll
        for (int i = 0; i < 8; i++) t += ws[i];
        g_x2[row] = t;
        g_rowsum[row] = 0.f;
    }
}

__global__ void splitc_kernel(const float* __restrict__ cen, __half* __restrict__ ch) {
    const int row = blockIdx.x;
    const float4* p = reinterpret_cast<const float4*>(cen + (size_t)row * D_);
    float s = 0.f;
    for (int i = threadIdx.x; i < D_ / 4; i += blockDim.x) {
        float4 v = p[i];
        s += v.x * v.x + v.y * v.y + v.z * v.z + v.w * v.w;
        __half h[4] = {__float2half(v.x), __float2half(v.y),
                       __float2half(v.z), __float2half(v.w)};
        *reinterpret_cast<uint2*>(ch + (size_t)row * D_ + i * 4) =
            *reinterpret_cast<uint2*>(h);
    }
    #pragma unroll
    for (int o = 16; o; o >>= 1) s += __shfl_xor_sync(0xffffffffu, s, o);
    __shared__ float ws[8];
    if ((threadIdx.x & 31) == 0) ws[threadIdx.x >> 5] = s;
    __syncthreads();
    if (threadIdx.x == 0) {
        float t = 0.f;
        #pragma unroll
        for (int i = 0; i < 8; i++) t += ws[i];
        g_c2[row] = t;
    }
}

__global__ void splitW_kernel(const float* __restrict__ W) {
    int i = blockIdx.x * blockDim.x + threadIdx.x;
    if (i >= KPAD_ * C_ / 4) return;
    int r = i >> 10;
    int c0 = (i & 1023) * 4;
    float f[4] = {0.f, 0.f, 0.f, 0.f};
    if (r < K_) {
        float4 v = *reinterpret_cast<const float4*>(W + (size_t)r * C_ + c0);
        f[0] = v.x; f[1] = v.y; f[2] = v.z; f[3] = v.w;
    }
    __half h[4] = {__float2half(f[0]), __float2half(f[1]),
                   __float2half(f[2]), __float2half(f[3])};
    *reinterpret_cast<uint2*>(g_wh + (size_t)r * C_ + c0) = *reinterpret_cast<uint2*>(h);
}

// ---------------------------------------------------------------------------
// fp16 1-pass GEMM: CTA tile 256x128, 8 warps (4x2, warp tile 64x64),
// K-chunk 64, 4-stage cp.async pipeline (loader runs 2 chunks ahead,
// wait<2> leaves >=2 groups of slack), one __syncthreads per chunk, 1 CTA/SM.
// MODE 0 (GEMM1): A=xh, B=ch. Epilogue: shifted RBF -> fp16 a' + rowsum.
// MODE 1 (GEMM2): A=a', B=wh. Epilogue: out = acc/rowsum + bias.
// ---------------------------------------------------------------------------
template <int KDIM, int MODE>
__global__ __launch_bounds__(256, 1) void gemm_f16_kernel(
    const __half* __restrict__ Ah, const __half* __restrict__ Bh,
    const float* __restrict__ beta, const float* __restrict__ bias,
    float* __restrict__ out)
{
    constexpr int NCH = KDIM / 64;
    extern __shared__ char smem[];
    const uint32_t sb = smem_u32(smem);
    const int tid = threadIdx.x;
    const int w = tid >> 5, lane = tid & 31;
    const int warp_m = w >> 1, warp_n = w & 1;   // 4x2 grid of 64x64 tiles
    const int bx = blockIdx.x, by = blockIdx.y;

    // ---- loader mapping ----
    const __half* srcA = Ah + (size_t)(by * 256 + tid) * KDIM;
    const int brow = tid & 127;
    const int bgb = (tid >> 7) * 4;
    const __half* srcB = Bh + (size_t)(bx * 128 + brow) * KDIM + bgb * 8;
    const uint32_t dA = tid * ROWB;
    const uint32_t dB = PART_A + brow * ROWB + bgb * 16;

    float acc[4][8][4];
    #pragma unroll
    for (int mt = 0; mt < 4; mt++)
        #pragma unroll
        for (int nt = 0; nt < 8; nt++)
            #pragma unroll
            for (int q = 0; q < 4; q++) acc[mt][nt][q] = 0.f;

#define S_ISSUE(stage, c) do {                                               \
        const uint32_t stb_ = sb + (stage) * S_STAGE;                        \
        const int co_ = (c) * 64;                                            \
        _Pragma("unroll")                                                    \
        for (int g_ = 0; g_ < 8; g_++)                                       \
            cp16(stb_ + dA + g_ * 16, srcA + co_ + g_ * 8);                  \
        _Pragma("unroll")                                                    \
        for (int g_ = 0; g_ < 4; g_++)                                       \
            cp16(stb_ + dB + g_ * 16, srcB + co_ + g_ * 8);                  \
        CP_COMMIT();                                                         \
    } while (0)

    S_ISSUE(0, 0);
    S_ISSUE(1, 1);
    S_ISSUE(2, 2);

    const uint32_t aoff = (uint32_t)(warp_m * 64 + (lane & 15)) * ROWB +
                          (uint32_t)((lane >> 4) << 3) * 2;
    const uint32_t boff = PART_A +
                          (uint32_t)(warp_n * 64 + (lane & 7) + ((lane >> 4) << 3)) * ROWB +
                          (uint32_t)(lane & 8) * 2;

    int st = 0, ld = 3;
    #pragma unroll 1
    for (int c = 0; c < NCH; c++) {
        cp_wait<2>();            // chunk c resident; up to 2 newer groups in flight
        __syncthreads();
        if (c + 3 < NCH) {
            S_ISSUE(ld, c + 3);
        } else {
            CP_COMMIT();         // empty group keeps wait<2> arithmetic exact
        }

        const uint32_t bufb = sb + st * S_STAGE;
        #pragma unroll
        for (int ks = 0; ks < 4; ks++) {
            const uint32_t kso = ks * 32;
            uint32_t AH[4][4], BB[8][2];
            #pragma unroll
            for (int mt = 0; mt < 4; mt++)
                ldsm_x4(AH[mt][0], AH[mt][1], AH[mt][2], AH[mt][3],
                        bufb + aoff + kso + mt * 16 * ROWB);
            #pragma unroll
            for (int np = 0; np < 4; np++) {
                uint32_t r0, r1, r2, r3;
                ldsm_x4(r0, r1, r2, r3,
                        bufb + boff + kso + np * 16 * ROWB);
                BB[np * 2][0] = r0; BB[np * 2][1] = r1;
                BB[np * 2 + 1][0] = r2; BB[np * 2 + 1][1] = r3;
            }
            #pragma unroll
            for (int mt = 0; mt < 4; mt++)
                #pragma unroll
                for (int nt = 0; nt < 8; nt++)
                    mma_f16(acc[mt][nt], AH[mt], BB[nt]);
        }
        st = (st + 1 == NSTAGE) ? 0 : st + 1;
        ld = (ld + 1 == NSTAGE) ? 0 : ld + 1;
    }
#undef S_ISSUE

    // ------------------------------ epilogue -------------------------------
    const int lr = lane >> 2;
    const int lc = (lane & 3) * 2;

    if (MODE == 0) {
        const float c2m = 2048.0f;   // E[c2]; softmax-shift only, non-critical
        #pragma unroll
        for (int mt = 0; mt < 4; mt++) {
            #pragma unroll
            for (int h = 0; h < 2; h++) {
                const int row = by * 256 + warp_m * 64 + mt * 16 + h * 8 + lr;
                const float x2v = g_x2[row];
                const float shift = sqrtf(x2v + c2m) - 4.0f;
                float rsum = 0.f;
                #pragma unroll
                for (int nt = 0; nt < 8; nt++) {
                    const int col = bx * 128 + warp_n * 64 + nt * 8 + lc;
                    const float dd0 = acc[mt][nt][h * 2 + 0];
                    const float dd1 = acc[mt][nt][h * 2 + 1];
                    float sq0 = x2v + g_c2[col]     - 2.f * dd0;
                    float sq1 = x2v + g_c2[col + 1] - 2.f * dd1;
                    float e0 = fminf(shift - beta[col]     * sqrtf(fmaxf(sq0, 0.f)), 10.f);
                    float e1 = fminf(shift - beta[col + 1] * sqrtf(fmaxf(sq1, 0.f)), 10.f);
                    float v0 = __expf(e0);
                    float v1 = __expf(e1);
                    rsum += v0 + v1;
                    __half h0 = __float2half(v0);
                    __half h1 = __float2half(v1);
                    uint32_t hp = (uint32_t)__half_as_ushort(h0) |
                                  ((uint32_t)__half_as_ushort(h1) << 16);
                    *reinterpret_cast<uint32_t*>(&g_ah[(size_t)row * C_ + col]) = hp;
                }
                rsum += __shfl_xor_sync(0xffffffffu, rsum, 1);
                rsum += __shfl_xor_sync(0xffffffffu, rsum, 2);
                if ((lane & 3) == 0) atomicAdd(&g_rowsum[row], rsum);
            }
        }
    } else {
        #pragma unroll
        for (int mt = 0; mt < 4; mt++) {
            #pragma unroll
            for (int h = 0; h < 2; h++) {
                const int row = by * 256 + warp_m * 64 + mt * 16 + h * 8 + lr;
                const float inv = 1.0f / g_rowsum[row];
                #pragma unroll
                for (int nt = 0; nt < 8; nt++) {
                    const int col = bx * 128 + warp_n * 64 + nt * 8 + lc;
                    if (col < K_) {
                        float2 bb = *reinterpret_cast<const float2*>(&bias[col]);
                        float2 o;
                        o.x = acc[mt][nt][h * 2 + 0] * inv + bb.x;
                        o.y = acc[mt][nt][h * 2 + 1] * inv + bb.y;
                        *reinterpret_cast<float2*>(&out[(size_t)row * K_ + col]) = o;
                    }
                }
            }
        }
    }
}

// ---------------------------------------------------------------------------
extern "C" void kernel_launch(void* const* d_in, const int* in_sizes, int n_in,
                              void* d_out, int out_size) {
    const float* x       = (const float*)d_in[0];
    const float* centers = (const float*)d_in[1];
    const float* beta    = (const float*)d_in[2];
    const float* W       = (const float*)d_in[3];
    const float* bias    = (const float*)d_in[4];
    float* out = (float*)d_out;

    __half *xh, *ch, *wh, *ah;
    cudaGetSymbolAddress((void**)&xh, g_xh);
    cudaGetSymbolAddress((void**)&ch, g_ch);
    cudaGetSymbolAddress((void**)&wh, g_wh);
    cudaGetSymbolAddress((void**)&ah, g_ah);

    cudaFuncSetAttribute(gemm_f16_kernel<D_, 0>,
                         cudaFuncAttributeMaxDynamicSharedMemorySize, S_SMEM);
    cudaFuncSetAttribute(gemm_f16_kernel<C_, 1>,
                         cudaFuncAttributeMaxDynamicSharedMemorySize, S_SMEM);

    splitx_kernel<<<B_, 256>>>(x, xh);
    splitc_kernel<<<C_, 256>>>(centers, ch);
    {
        int n4 = KPAD_ * C_ / 4;
        splitW_kernel<<<(n4 + 255) / 256, 256>>>(W);
    }

    dim3 g1(C_ / 128, B_ / 256);            // (32, 32)
    gemm_f16_kernel<D_, 0><<<g1, 256, S_SMEM>>>(xh, ch, beta, bias, out);

    dim3 g2(KPAD_ / 128, B_ / 256);         // (8, 32)
    gemm_f16_kernel<C_, 1><<<g2, 256, S_SMEM>>>(ah, wh, beta, bias, out);
}